// round 9
// baseline (speedup 1.0000x reference)
#include <cuda_runtime.h>
#include <cuda_bf16.h>
#include <math.h>
#include <stdint.h>

#define NQ   10001          // distinct quantized times: floor(t/0.1), t in [0,1000)
#define NQB  10016          // padded bin count
#define DD   1024
#define RR   256
#define QT   128            // q tile (block M)
#define DT   64             // d tile (block N)
#define NQT  10112          // 79 * 128 q-tiles
#define SPH  136            // padded bf16 smem row stride for K=128 stage (272 B)

// Scratch (device globals — no allocation allowed)
__device__ __nv_bfloat16 g_redH[NQT * RR];
__device__ __nv_bfloat16 g_redL[NQT * RR];
__device__ __nv_bfloat16 g_WeH[DD * RR];
__device__ __nv_bfloat16 g_WeL[DD * RR];
__device__ __align__(128) float g_table[NQ * DD];   // LUT [q][d], ~41 MB
__device__ int g_hist[NQB];
__device__ int g_off[NQB + 1];
__device__ int g_cursor[NQB];
__device__ int g_idx[262144 + 64];                  // B rows (B = 262144 for this problem)

// smem offsets for the build kernel (two-stage K: 128 per stage)
#define OFF_AH 0
#define OFF_AL (QT * SPH * 2)                 // 34816
#define OFF_BH (2 * QT * SPH * 2)             // 69632
#define OFF_BL (2 * QT * SPH * 2 + DT * SPH * 2)
#define SMEM_MMA (2 * QT * SPH * 2 + 2 * DT * SPH * 2)   // 104448

// ---------------------------------------------------------------------------
__device__ __forceinline__ uint32_t smem_u32(const void* p) {
    uint32_t a;
    asm("{ .reg .u64 t; cvta.to.shared.u64 t, %1; cvt.u32.u64 %0, t; }"
        : "=r"(a) : "l"(p));
    return a;
}
__device__ __forceinline__ void ldm4(uint32_t* r, uint32_t addr) {
    asm volatile("ldmatrix.sync.aligned.m8n8.x4.shared.b16 {%0,%1,%2,%3}, [%4];"
                 : "=r"(r[0]), "=r"(r[1]), "=r"(r[2]), "=r"(r[3]) : "r"(addr));
}
__device__ __forceinline__ void mma_bf16(float* c, const uint32_t* a,
                                         uint32_t b0, uint32_t b1) {
    asm volatile(
        "mma.sync.aligned.m16n8k16.row.col.f32.bf16.bf16.f32 "
        "{%0,%1,%2,%3}, {%4,%5,%6,%7}, {%8,%9}, {%0,%1,%2,%3};"
        : "+f"(c[0]), "+f"(c[1]), "+f"(c[2]), "+f"(c[3])
        : "r"(a[0]), "r"(a[1]), "r"(a[2]), "r"(a[3]), "r"(b0), "r"(b1));
}
__device__ __forceinline__ int qof(float tv) {
    int q = (int)floorf(__fdiv_rn(tv, 0.1f));   // IEEE div under any fast-math
    return max(0, min(q, NQ - 1));
}

// ---------------------------------------------------------------------------
// Prep A: red[q][r] = relu(cos(tq*wr+wrb)), split to hi/lo bf16.
__global__ void k_prep_red(const float* __restrict__ wr,
                           const float* __restrict__ wrb) {
    int q = blockIdx.x;
    int r = threadIdx.x;
    int qc = min(q, NQ - 1);
    float tq  = (float)qc * 0.1f;             // matches floor(t/0.1f)*0.1f
    float arg = fmaf(tq, wr[r], wrb[r]);
    // Cody-Waite 2*pi reduction (|arg| <= ~153): exact under fast-math
    float k   = rintf(arg * 0.15915494309189535f);
    float red = fmaf(-k, 6.28125f, arg);
    red       = fmaf(-k, 1.9353071795864769e-3f, red);
    float v   = cosf(red);
    v = v > 0.0f ? v : 0.0f;
    __nv_bfloat16 h = __float2bfloat16(v);
    __nv_bfloat16 l = __float2bfloat16(v - __bfloat162float(h));
    g_redH[q * RR + r] = h;
    g_redL[q * RR + r] = l;
}

// Prep B: split w_expand [d][r] into hi/lo bf16 (already K-major).
__global__ void k_prep_we(const float* __restrict__ we) {
    int d = blockIdx.x;
    int r = threadIdx.x;
    float v = we[d * RR + r];
    __nv_bfloat16 h = __float2bfloat16(v);
    __nv_bfloat16 l = __float2bfloat16(v - __bfloat162float(h));
    g_WeH[d * RR + r] = h;
    g_WeL[d * RR + r] = l;
}

// ---------------------------------------------------------------------------
// Counting sort of rows by q: zero -> hist -> scan -> fill
__global__ void k_zero() {
    int i = blockIdx.x * 256 + threadIdx.x;
    if (i < NQB) g_hist[i] = 0;
}
__global__ void k_hist(const float* __restrict__ tt, int B) {
    int b = blockIdx.x * 256 + threadIdx.x;
    if (b < B) atomicAdd(&g_hist[qof(tt[b])], 1);
}
// Single-block exclusive scan over NQB bins (1024 thr x chunk 10).
__global__ void __launch_bounds__(1024) k_scan() {
    __shared__ int s[1024];
    int tid = threadIdx.x;
    int base = tid * 10;
    int local[10];
    int sum = 0;
#pragma unroll
    for (int c = 0; c < 10; ++c) {
        int i = base + c;
        int v = (i < NQB) ? g_hist[i] : 0;
        local[c] = sum;
        sum += v;
    }
    s[tid] = sum;
    __syncthreads();
    for (int off = 1; off < 1024; off <<= 1) {
        int v = (tid >= off) ? s[tid - off] : 0;
        __syncthreads();
        s[tid] += v;
        __syncthreads();
    }
    int pre = (tid > 0) ? s[tid - 1] : 0;
#pragma unroll
    for (int c = 0; c < 10; ++c) {
        int i = base + c;
        if (i < NQB) {
            int e = pre + local[c];
            g_off[i] = e;
            g_cursor[i] = e;
        }
    }
    if (tid == 1023) g_off[NQB] = s[1023];
}
__global__ void k_fill(const float* __restrict__ tt, int B) {
    int b = blockIdx.x * 256 + threadIdx.x;
    if (b < B) {
        int pos = atomicAdd(&g_cursor[qof(tt[b])], 1);
        g_idx[pos] = b;
    }
}

// ---------------------------------------------------------------------------
// HMMA table build: two-stage K staging (smem halved -> 2 CTAs/SM).
// 8 warps (4m x 2n); warp tile 32q x 32d; 3 split-bf16 products.
__global__ void __launch_bounds__(256) k_mma_table(const float* __restrict__ web) {
    extern __shared__ char dsm[];
    __shared__ float sWeb[DT];
    uint32_t sb = smem_u32(dsm);
    int tid = threadIdx.x, lane = tid & 31, wid = tid >> 5;
    int qt0 = blockIdx.x * QT, dt0 = blockIdx.y * DT;

    if (tid < DT) sWeb[tid] = web[dt0 + tid];

    int wm = wid & 3, wn = wid >> 2;
    int lrow  = lane & 15;
    int khalf = (lane >> 4) * 8;

    uint32_t aHb = sb + OFF_AH + (uint32_t)((wm * 32 + lrow) * SPH + khalf) * 2;
    uint32_t aLb = sb + OFF_AL + (uint32_t)((wm * 32 + lrow) * SPH + khalf) * 2;
    uint32_t bHb = sb + OFF_BH + (uint32_t)((wn * 32 + lrow) * SPH + khalf) * 2;
    uint32_t bLb = sb + OFF_BL + (uint32_t)((wn * 32 + lrow) * SPH + khalf) * 2;

    float acc[2][4][4];
#pragma unroll
    for (int m = 0; m < 2; ++m)
#pragma unroll
        for (int j = 0; j < 4; ++j)
#pragma unroll
            for (int c = 0; c < 4; ++c) acc[m][j][c] = 0.0f;

    for (int h = 0; h < 2; ++h) {
        // stage K half h: A 128x128, B 64x128 (H and L)
#pragma unroll 4
        for (int i = tid; i < QT * 16; i += 256) {
            int row = i >> 4, u = i & 15;
            size_t   src = (size_t)(qt0 + row) * RR + h * 128 + u * 8;
            uint32_t dst = (uint32_t)(row * SPH + u * 8) * 2;
            *(uint4*)(dsm + OFF_AH + dst) = *(const uint4*)(g_redH + src);
            *(uint4*)(dsm + OFF_AL + dst) = *(const uint4*)(g_redL + src);
        }
#pragma unroll 2
        for (int i = tid; i < DT * 16; i += 256) {
            int row = i >> 4, u = i & 15;
            size_t   src = (size_t)(dt0 + row) * RR + h * 128 + u * 8;
            uint32_t dst = (uint32_t)(row * SPH + u * 8) * 2;
            *(uint4*)(dsm + OFF_BH + dst) = *(const uint4*)(g_WeH + src);
            *(uint4*)(dsm + OFF_BL + dst) = *(const uint4*)(g_WeL + src);
        }
        __syncthreads();

#pragma unroll
        for (int ks = 0; ks < 8; ++ks) {
            uint32_t ko = (uint32_t)(ks * 16) * 2;
            uint32_t aH[2][4], aL[2][4], bH[2][4], bL[2][4];
            ldm4(aH[0], aHb + ko);
            ldm4(aH[1], aHb + ko + 16 * SPH * 2);
            ldm4(aL[0], aLb + ko);
            ldm4(aL[1], aLb + ko + 16 * SPH * 2);
            ldm4(bH[0], bHb + ko);
            ldm4(bH[1], bHb + ko + 16 * SPH * 2);
            ldm4(bL[0], bLb + ko);
            ldm4(bL[1], bLb + ko + 16 * SPH * 2);
#pragma unroll
            for (int m = 0; m < 2; ++m) {
#pragma unroll
                for (int j = 0; j < 4; ++j) {
                    int g = j >> 1, p = j & 1;
                    mma_bf16(acc[m][j], aH[m], bH[g][p], bH[g][p + 2]);  // hh
                    mma_bf16(acc[m][j], aH[m], bL[g][p], bL[g][p + 2]);  // hl
                    mma_bf16(acc[m][j], aL[m], bH[g][p], bH[g][p + 2]);  // lh
                }
            }
        }
        __syncthreads();
    }

    // Epilogue: +bias, direct fp32 stores (float2 per fragment row).
    int crow = lane >> 2;
    int ccol = (lane & 3) * 2;
#pragma unroll
    for (int m = 0; m < 2; ++m) {
        int r0 = qt0 + wm * 32 + m * 16 + crow;
#pragma unroll
        for (int j = 0; j < 4; ++j) {
            int cl = wn * 32 + j * 8 + ccol;
            float b0 = sWeb[cl], b1 = sWeb[cl + 1];
            if (r0 < NQ) {
                float2 o = { acc[m][j][0] + b0, acc[m][j][1] + b1 };
                *(float2*)(g_table + (size_t)r0 * DD + dt0 + cl) = o;
            }
            if (r0 + 8 < NQ) {
                float2 o = { acc[m][j][2] + b0, acc[m][j][3] + b1 };
                *(float2*)(g_table + (size_t)(r0 + 8) * DD + dt0 + cl) = o;
            }
        }
    }
}

// ---------------------------------------------------------------------------
// Bin scatter: one block per q. Load table row ONCE (4 KB -> registers),
// write it to all rows in the bin. L2 read traffic: 41 MB instead of 1.07 GB.
__global__ void __launch_bounds__(256) k_scatter(float4* __restrict__ out) {
    int q = blockIdx.x;
    int start = g_off[q];
    int cnt   = g_off[q + 1] - start;
    if (cnt == 0) return;
    float4 v = ((const float4*)g_table)[(size_t)q * (DD / 4) + threadIdx.x];
    for (int j = 0; j < cnt; ++j) {
        int b = __ldg(g_idx + start + j);      // warp-uniform, L1-cached
        __stcs(out + (size_t)b * (DD / 4) + threadIdx.x, v);
    }
}

// ---------------------------------------------------------------------------
extern "C" void kernel_launch(void* const* d_in, const int* in_sizes, int n_in,
                              void* d_out, int out_size) {
    const float* t   = (const float*)d_in[0];   // (B,)
    const float* wr  = (const float*)d_in[1];   // (R,1)
    const float* wrb = (const float*)d_in[2];   // (R,)
    const float* we  = (const float*)d_in[3];   // (D,R)
    const float* web = (const float*)d_in[4];   // (D,)
    float* out = (float*)d_out;
    int B = in_sizes[0];

    cudaFuncSetAttribute(k_mma_table,
                         cudaFuncAttributeMaxDynamicSharedMemorySize, SMEM_MMA);

    k_zero<<<(NQB + 255) / 256, 256>>>();
    k_prep_red<<<NQT, RR>>>(wr, wrb);
    k_prep_we<<<DD, RR>>>(we);
    k_hist<<<(B + 255) / 256, 256>>>(t, B);
    k_scan<<<1, 1024>>>();
    k_fill<<<(B + 255) / 256, 256>>>(t, B);
    k_mma_table<<<dim3(NQT / QT, DD / DT), 256, SMEM_MMA>>>(web);
    k_scatter<<<NQ, 256>>>((float4*)out);
}

// round 10
// speedup vs baseline: 1.3979x; 1.3979x over previous
#include <cuda_runtime.h>
#include <cuda_bf16.h>
#include <math.h>
#include <stdint.h>

#define NQ   10001          // distinct quantized times: floor(t/0.1), t in [0,1000)
#define DD   1024
#define RR   256
#define QT   128            // q tile (block M)
#define DT   64             // d tile (block N)
#define NQT  10112          // 79 * 128 q-tiles
#define ROWS_PER_BLK 8      // scatter rows per block
#define SPH  136            // padded bf16 smem row stride for K=128 stage (272 B)

// Scratch (device globals — no allocation allowed)
__device__ __nv_bfloat16 g_redH[NQT * RR];
__device__ __nv_bfloat16 g_redL[NQT * RR];
__device__ __nv_bfloat16 g_WeH[DD * RR];
__device__ __nv_bfloat16 g_WeL[DD * RR];
__device__ __align__(128) float g_table[NQ * DD];   // LUT [q][d], ~41 MB

// smem offsets for the build kernel (two-stage K: 128 per stage, 2 CTAs/SM)
#define OFF_AH 0
#define OFF_AL (QT * SPH * 2)                 // 34816
#define OFF_BH (2 * QT * SPH * 2)             // 69632
#define OFF_BL (2 * QT * SPH * 2 + DT * SPH * 2)
#define SMEM_MMA (2 * QT * SPH * 2 + 2 * DT * SPH * 2)   // 104448

// ---------------------------------------------------------------------------
__device__ __forceinline__ uint32_t smem_u32(const void* p) {
    uint32_t a;
    asm("{ .reg .u64 t; cvta.to.shared.u64 t, %1; cvt.u32.u64 %0, t; }"
        : "=r"(a) : "l"(p));
    return a;
}
__device__ __forceinline__ void ldm4(uint32_t* r, uint32_t addr) {
    asm volatile("ldmatrix.sync.aligned.m8n8.x4.shared.b16 {%0,%1,%2,%3}, [%4];"
                 : "=r"(r[0]), "=r"(r[1]), "=r"(r[2]), "=r"(r[3]) : "r"(addr));
}
__device__ __forceinline__ void mma_bf16(float* c, const uint32_t* a,
                                         uint32_t b0, uint32_t b1) {
    asm volatile(
        "mma.sync.aligned.m16n8k16.row.col.f32.bf16.bf16.f32 "
        "{%0,%1,%2,%3}, {%4,%5,%6,%7}, {%8,%9}, {%0,%1,%2,%3};"
        : "+f"(c[0]), "+f"(c[1]), "+f"(c[2]), "+f"(c[3])
        : "r"(a[0]), "r"(a[1]), "r"(a[2]), "r"(a[3]), "r"(b0), "r"(b1));
}

// ---------------------------------------------------------------------------
// Fused prep: blocks [0, NQT) -> red rows; blocks [NQT, NQT+DD) -> we rows.
__global__ void k_prep(const float* __restrict__ wr,
                       const float* __restrict__ wrb,
                       const float* __restrict__ we) {
    int blk = blockIdx.x;
    int r = threadIdx.x;
    if (blk < NQT) {
        int qc = min(blk, NQ - 1);                // pad rows clamped (never stored)
        float tq  = (float)qc * 0.1f;             // matches floor(t/0.1f)*0.1f
        float arg = fmaf(tq, wr[r], wrb[r]);
        // Cody-Waite 2*pi reduction (|arg| <= ~153): exact under fast-math
        float k   = rintf(arg * 0.15915494309189535f);
        float red = fmaf(-k, 6.28125f, arg);
        red       = fmaf(-k, 1.9353071795864769e-3f, red);
        float v   = cosf(red);
        v = v > 0.0f ? v : 0.0f;
        __nv_bfloat16 h = __float2bfloat16(v);
        __nv_bfloat16 l = __float2bfloat16(v - __bfloat162float(h));
        g_redH[blk * RR + r] = h;
        g_redL[blk * RR + r] = l;
    } else {
        int d = blk - NQT;
        float v = we[d * RR + r];
        __nv_bfloat16 h = __float2bfloat16(v);
        __nv_bfloat16 l = __float2bfloat16(v - __bfloat162float(h));
        g_WeH[d * RR + r] = h;
        g_WeL[d * RR + r] = l;
    }
}

// ---------------------------------------------------------------------------
// HMMA table build: two-stage K staging (104 KB smem -> 2 CTAs/SM so one
// CTA's global loads overlap the other's tensor work).
// 8 warps (4m x 2n); warp tile 32q x 32d; 3 split-bf16 products (hh+hl+lh).
// grid (79, 16), 256 threads.
__global__ void __launch_bounds__(256) k_mma_table(const float* __restrict__ web) {
    extern __shared__ char dsm[];
    __shared__ float sWeb[DT];
    uint32_t sb = smem_u32(dsm);
    int tid = threadIdx.x, lane = tid & 31, wid = tid >> 5;
    int qt0 = blockIdx.x * QT, dt0 = blockIdx.y * DT;

    if (tid < DT) sWeb[tid] = web[dt0 + tid];

    int wm = wid & 3, wn = wid >> 2;
    int lrow  = lane & 15;
    int khalf = (lane >> 4) * 8;

    uint32_t aHb = sb + OFF_AH + (uint32_t)((wm * 32 + lrow) * SPH + khalf) * 2;
    uint32_t aLb = sb + OFF_AL + (uint32_t)((wm * 32 + lrow) * SPH + khalf) * 2;
    uint32_t bHb = sb + OFF_BH + (uint32_t)((wn * 32 + lrow) * SPH + khalf) * 2;
    uint32_t bLb = sb + OFF_BL + (uint32_t)((wn * 32 + lrow) * SPH + khalf) * 2;

    float acc[2][4][4];
#pragma unroll
    for (int m = 0; m < 2; ++m)
#pragma unroll
        for (int j = 0; j < 4; ++j)
#pragma unroll
            for (int c = 0; c < 4; ++c) acc[m][j][c] = 0.0f;

    for (int h = 0; h < 2; ++h) {
        // stage K half h: A 128x128 (H/L), B 64x128 (H/L)
#pragma unroll 4
        for (int i = tid; i < QT * 16; i += 256) {
            int row = i >> 4, u = i & 15;
            size_t   src = (size_t)(qt0 + row) * RR + h * 128 + u * 8;
            uint32_t dst = (uint32_t)(row * SPH + u * 8) * 2;
            *(uint4*)(dsm + OFF_AH + dst) = *(const uint4*)(g_redH + src);
            *(uint4*)(dsm + OFF_AL + dst) = *(const uint4*)(g_redL + src);
        }
#pragma unroll 2
        for (int i = tid; i < DT * 16; i += 256) {
            int row = i >> 4, u = i & 15;
            size_t   src = (size_t)(dt0 + row) * RR + h * 128 + u * 8;
            uint32_t dst = (uint32_t)(row * SPH + u * 8) * 2;
            *(uint4*)(dsm + OFF_BH + dst) = *(const uint4*)(g_WeH + src);
            *(uint4*)(dsm + OFF_BL + dst) = *(const uint4*)(g_WeL + src);
        }
        __syncthreads();

#pragma unroll
        for (int ks = 0; ks < 8; ++ks) {
            uint32_t ko = (uint32_t)(ks * 16) * 2;
            uint32_t aH[2][4], aL[2][4], bH[2][4], bL[2][4];
            ldm4(aH[0], aHb + ko);
            ldm4(aH[1], aHb + ko + 16 * SPH * 2);
            ldm4(aL[0], aLb + ko);
            ldm4(aL[1], aLb + ko + 16 * SPH * 2);
            ldm4(bH[0], bHb + ko);
            ldm4(bH[1], bHb + ko + 16 * SPH * 2);
            ldm4(bL[0], bLb + ko);
            ldm4(bL[1], bLb + ko + 16 * SPH * 2);
#pragma unroll
            for (int m = 0; m < 2; ++m) {
#pragma unroll
                for (int j = 0; j < 4; ++j) {
                    int g = j >> 1, p = j & 1;
                    mma_bf16(acc[m][j], aH[m], bH[g][p], bH[g][p + 2]);  // hh
                    mma_bf16(acc[m][j], aH[m], bL[g][p], bL[g][p + 2]);  // hl
                    mma_bf16(acc[m][j], aL[m], bH[g][p], bH[g][p + 2]);  // lh
                }
            }
        }
        __syncthreads();
    }

    // Epilogue: +bias, direct fp32 stores (float2 per fragment row).
    int crow = lane >> 2;
    int ccol = (lane & 3) * 2;
#pragma unroll
    for (int m = 0; m < 2; ++m) {
        int r0 = qt0 + wm * 32 + m * 16 + crow;
#pragma unroll
        for (int j = 0; j < 4; ++j) {
            int cl = wn * 32 + j * 8 + ccol;
            float b0 = sWeb[cl], b1 = sWeb[cl + 1];
            if (r0 < NQ) {
                float2 o = { acc[m][j][0] + b0, acc[m][j][1] + b1 };
                *(float2*)(g_table + (size_t)r0 * DD + dt0 + cl) = o;
            }
            if (r0 + 8 < NQ) {
                float2 o = { acc[m][j][2] + b0, acc[m][j][3] + b1 };
                *(float2*)(g_table + (size_t)(r0 + 8) * DD + dt0 + cl) = o;
            }
        }
    }
}

// ---------------------------------------------------------------------------
// Scatter (R8 proven form): out[b][:] = table[q(b)][:]
// 8 rows/block, 256 threads; 8 independent LDG.128 then 8 STG.128 streaming.
// Sequential writes (consecutive blocks -> consecutive b) keep DRAM-friendly.
__global__ void __launch_bounds__(256) k_scatter(const float* __restrict__ tt,
                                                 float4* __restrict__ out) {
    __shared__ int qidx[ROWS_PER_BLK];
    int b0 = blockIdx.x * ROWS_PER_BLK;
    if (threadIdx.x < ROWS_PER_BLK) {
        float tv = __ldg(tt + b0 + threadIdx.x);
        int q = (int)floorf(__fdiv_rn(tv, 0.1f));   // IEEE div under any fast-math
        qidx[threadIdx.x] = max(0, min(q, NQ - 1));
    }
    __syncthreads();

    const float4* tab = (const float4*)g_table;
    float4 v[ROWS_PER_BLK];
#pragma unroll
    for (int i = 0; i < ROWS_PER_BLK; ++i)
        v[i] = tab[(size_t)qidx[i] * (DD / 4) + threadIdx.x];
#pragma unroll
    for (int i = 0; i < ROWS_PER_BLK; ++i)
        __stcs(out + ((size_t)(b0 + i) * (DD / 4) + threadIdx.x), v[i]);
}

// ---------------------------------------------------------------------------
extern "C" void kernel_launch(void* const* d_in, const int* in_sizes, int n_in,
                              void* d_out, int out_size) {
    const float* t   = (const float*)d_in[0];   // (B,)
    const float* wr  = (const float*)d_in[1];   // (R,1)
    const float* wrb = (const float*)d_in[2];   // (R,)
    const float* we  = (const float*)d_in[3];   // (D,R)
    const float* web = (const float*)d_in[4];   // (D,)
    float* out = (float*)d_out;
    int B = in_sizes[0];

    cudaFuncSetAttribute(k_mma_table,
                         cudaFuncAttributeMaxDynamicSharedMemorySize, SMEM_MMA);

    k_prep<<<NQT + DD, RR>>>(wr, wrb, we);
    k_mma_table<<<dim3(NQT / QT, DD / DT), 256, SMEM_MMA>>>(web);
    k_scatter<<<B / ROWS_PER_BLK, 256>>>(t, (float4*)out);
}

// round 11
// speedup vs baseline: 1.6041x; 1.1475x over previous
#include <cuda_runtime.h>
#include <cuda_bf16.h>
#include <cuda_fp16.h>
#include <math.h>
#include <stdint.h>

#define NQ   10001          // distinct quantized times: floor(t/0.1), t in [0,1000)
#define DD   1024
#define RR   256
#define QT   128            // q tile (block M)
#define DT   64             // d tile (block N)
#define NQT  10112          // 79 * 128 q-tiles
#define ROWS_PER_BLK 8      // scatter rows per block
#define SPH  136            // padded bf16 smem row stride for K=128 stage (272 B)

// Scratch (device globals — no allocation allowed)
__device__ __nv_bfloat16 g_redH[NQT * RR];
__device__ __nv_bfloat16 g_redL[NQT * RR];
__device__ __nv_bfloat16 g_WeH[DD * RR];
__device__ __nv_bfloat16 g_WeL[DD * RR];
__device__ __align__(128) __half g_table[NQ * DD];   // LUT [q][d], fp16, ~20.5 MB

// smem offsets for the build kernel (two-stage K: 128 per stage, 2 CTAs/SM)
#define OFF_AH 0
#define OFF_AL (QT * SPH * 2)                 // 34816
#define OFF_BH (2 * QT * SPH * 2)             // 69632
#define OFF_BL (2 * QT * SPH * 2 + DT * SPH * 2)
#define SMEM_MMA (2 * QT * SPH * 2 + 2 * DT * SPH * 2)   // 104448

// ---------------------------------------------------------------------------
__device__ __forceinline__ uint32_t smem_u32(const void* p) {
    uint32_t a;
    asm("{ .reg .u64 t; cvta.to.shared.u64 t, %1; cvt.u32.u64 %0, t; }"
        : "=r"(a) : "l"(p));
    return a;
}
__device__ __forceinline__ void ldm4(uint32_t* r, uint32_t addr) {
    asm volatile("ldmatrix.sync.aligned.m8n8.x4.shared.b16 {%0,%1,%2,%3}, [%4];"
                 : "=r"(r[0]), "=r"(r[1]), "=r"(r[2]), "=r"(r[3]) : "r"(addr));
}
__device__ __forceinline__ void mma_bf16(float* c, const uint32_t* a,
                                         uint32_t b0, uint32_t b1) {
    asm volatile(
        "mma.sync.aligned.m16n8k16.row.col.f32.bf16.bf16.f32 "
        "{%0,%1,%2,%3}, {%4,%5,%6,%7}, {%8,%9}, {%0,%1,%2,%3};"
        : "+f"(c[0]), "+f"(c[1]), "+f"(c[2]), "+f"(c[3])
        : "r"(a[0]), "r"(a[1]), "r"(a[2]), "r"(a[3]), "r"(b0), "r"(b1));
}

// ---------------------------------------------------------------------------
// Fused prep: blocks [0, NQT) -> red rows; blocks [NQT, NQT+DD) -> we rows.
__global__ void k_prep(const float* __restrict__ wr,
                       const float* __restrict__ wrb,
                       const float* __restrict__ we) {
    int blk = blockIdx.x;
    int r = threadIdx.x;
    if (blk < NQT) {
        int qc = min(blk, NQ - 1);                // pad rows clamped (never stored)
        float tq  = (float)qc * 0.1f;             // matches floor(t/0.1f)*0.1f
        float arg = fmaf(tq, wr[r], wrb[r]);
        // Cody-Waite 2*pi reduction (|arg| <= ~153): exact under fast-math
        float k   = rintf(arg * 0.15915494309189535f);
        float red = fmaf(-k, 6.28125f, arg);
        red       = fmaf(-k, 1.9353071795864769e-3f, red);
        float v   = cosf(red);
        v = v > 0.0f ? v : 0.0f;
        __nv_bfloat16 h = __float2bfloat16(v);
        __nv_bfloat16 l = __float2bfloat16(v - __bfloat162float(h));
        g_redH[blk * RR + r] = h;
        g_redL[blk * RR + r] = l;
    } else {
        int d = blk - NQT;
        float v = we[d * RR + r];
        __nv_bfloat16 h = __float2bfloat16(v);
        __nv_bfloat16 l = __float2bfloat16(v - __bfloat162float(h));
        g_WeH[d * RR + r] = h;
        g_WeL[d * RR + r] = l;
    }
}

// ---------------------------------------------------------------------------
// HMMA table build: two-stage K staging (104 KB smem -> 2 CTAs/SM).
// 8 warps (4m x 2n); warp tile 32q x 32d; 3 split-bf16 products (hh+hl+lh).
// Epilogue stores fp16 (half2) — halves table write + scatter read traffic.
// grid (79, 16), 256 threads.
__global__ void __launch_bounds__(256) k_mma_table(const float* __restrict__ web) {
    extern __shared__ char dsm[];
    __shared__ float sWeb[DT];
    uint32_t sb = smem_u32(dsm);
    int tid = threadIdx.x, lane = tid & 31, wid = tid >> 5;
    int qt0 = blockIdx.x * QT, dt0 = blockIdx.y * DT;

    if (tid < DT) sWeb[tid] = web[dt0 + tid];

    int wm = wid & 3, wn = wid >> 2;
    int lrow  = lane & 15;
    int khalf = (lane >> 4) * 8;

    uint32_t aHb = sb + OFF_AH + (uint32_t)((wm * 32 + lrow) * SPH + khalf) * 2;
    uint32_t aLb = sb + OFF_AL + (uint32_t)((wm * 32 + lrow) * SPH + khalf) * 2;
    uint32_t bHb = sb + OFF_BH + (uint32_t)((wn * 32 + lrow) * SPH + khalf) * 2;
    uint32_t bLb = sb + OFF_BL + (uint32_t)((wn * 32 + lrow) * SPH + khalf) * 2;

    float acc[2][4][4];
#pragma unroll
    for (int m = 0; m < 2; ++m)
#pragma unroll
        for (int j = 0; j < 4; ++j)
#pragma unroll
            for (int c = 0; c < 4; ++c) acc[m][j][c] = 0.0f;

    for (int h = 0; h < 2; ++h) {
        // stage K half h: A 128x128 (H/L), B 64x128 (H/L)
#pragma unroll 4
        for (int i = tid; i < QT * 16; i += 256) {
            int row = i >> 4, u = i & 15;
            size_t   src = (size_t)(qt0 + row) * RR + h * 128 + u * 8;
            uint32_t dst = (uint32_t)(row * SPH + u * 8) * 2;
            *(uint4*)(dsm + OFF_AH + dst) = *(const uint4*)(g_redH + src);
            *(uint4*)(dsm + OFF_AL + dst) = *(const uint4*)(g_redL + src);
        }
#pragma unroll 2
        for (int i = tid; i < DT * 16; i += 256) {
            int row = i >> 4, u = i & 15;
            size_t   src = (size_t)(dt0 + row) * RR + h * 128 + u * 8;
            uint32_t dst = (uint32_t)(row * SPH + u * 8) * 2;
            *(uint4*)(dsm + OFF_BH + dst) = *(const uint4*)(g_WeH + src);
            *(uint4*)(dsm + OFF_BL + dst) = *(const uint4*)(g_WeL + src);
        }
        __syncthreads();

#pragma unroll
        for (int ks = 0; ks < 8; ++ks) {
            uint32_t ko = (uint32_t)(ks * 16) * 2;
            uint32_t aH[2][4], aL[2][4], bH[2][4], bL[2][4];
            ldm4(aH[0], aHb + ko);
            ldm4(aH[1], aHb + ko + 16 * SPH * 2);
            ldm4(aL[0], aLb + ko);
            ldm4(aL[1], aLb + ko + 16 * SPH * 2);
            ldm4(bH[0], bHb + ko);
            ldm4(bH[1], bHb + ko + 16 * SPH * 2);
            ldm4(bL[0], bLb + ko);
            ldm4(bL[1], bLb + ko + 16 * SPH * 2);
#pragma unroll
            for (int m = 0; m < 2; ++m) {
#pragma unroll
                for (int j = 0; j < 4; ++j) {
                    int g = j >> 1, p = j & 1;
                    mma_bf16(acc[m][j], aH[m], bH[g][p], bH[g][p + 2]);  // hh
                    mma_bf16(acc[m][j], aH[m], bL[g][p], bL[g][p + 2]);  // hl
                    mma_bf16(acc[m][j], aL[m], bH[g][p], bH[g][p + 2]);  // lh
                }
            }
        }
        __syncthreads();
    }

    // Epilogue: +bias, convert to fp16, half2 stores.
    int crow = lane >> 2;
    int ccol = (lane & 3) * 2;
#pragma unroll
    for (int m = 0; m < 2; ++m) {
        int r0 = qt0 + wm * 32 + m * 16 + crow;
#pragma unroll
        for (int j = 0; j < 4; ++j) {
            int cl = wn * 32 + j * 8 + ccol;
            float b0 = sWeb[cl], b1 = sWeb[cl + 1];
            if (r0 < NQ) {
                __half2 o = __floats2half2_rn(acc[m][j][0] + b0, acc[m][j][1] + b1);
                *(__half2*)(g_table + (size_t)r0 * DD + dt0 + cl) = o;
            }
            if (r0 + 8 < NQ) {
                __half2 o = __floats2half2_rn(acc[m][j][2] + b0, acc[m][j][3] + b1);
                *(__half2*)(g_table + (size_t)(r0 + 8) * DD + dt0 + cl) = o;
            }
        }
    }
}

// ---------------------------------------------------------------------------
// Scatter: out[b][:] = fp32(table_fp16[q(b)][:])
// 8 rows/block, 256 threads; 8 independent 8B loads (halved read traffic),
// cvt to fp32, 8 STG.128 streaming. Sequential writes stay DRAM-friendly.
__global__ void __launch_bounds__(256) k_scatter(const float* __restrict__ tt,
                                                 float4* __restrict__ out) {
    __shared__ int qidx[ROWS_PER_BLK];
    int b0 = blockIdx.x * ROWS_PER_BLK;
    if (threadIdx.x < ROWS_PER_BLK) {
        float tv = __ldg(tt + b0 + threadIdx.x);
        int q = (int)floorf(__fdiv_rn(tv, 0.1f));   // IEEE div under any fast-math
        qidx[threadIdx.x] = max(0, min(q, NQ - 1));
    }
    __syncthreads();

    const uint2* tab = (const uint2*)g_table;       // 4 halves per uint2
    uint2 v[ROWS_PER_BLK];
#pragma unroll
    for (int i = 0; i < ROWS_PER_BLK; ++i)
        v[i] = tab[(size_t)qidx[i] * (DD / 4) + threadIdx.x];
#pragma unroll
    for (int i = 0; i < ROWS_PER_BLK; ++i) {
        float2 f01 = __half22float2(*(const __half2*)&v[i].x);
        float2 f23 = __half22float2(*(const __half2*)&v[i].y);
        float4 o = { f01.x, f01.y, f23.x, f23.y };
        __stcs(out + ((size_t)(b0 + i) * (DD / 4) + threadIdx.x), o);
    }
}

// ---------------------------------------------------------------------------
extern "C" void kernel_launch(void* const* d_in, const int* in_sizes, int n_in,
                              void* d_out, int out_size) {
    const float* t   = (const float*)d_in[0];   // (B,)
    const float* wr  = (const float*)d_in[1];   // (R,1)
    const float* wrb = (const float*)d_in[2];   // (R,)
    const float* we  = (const float*)d_in[3];   // (D,R)
    const float* web = (const float*)d_in[4];   // (D,)
    float* out = (float*)d_out;
    int B = in_sizes[0];

    cudaFuncSetAttribute(k_mma_table,
                         cudaFuncAttributeMaxDynamicSharedMemorySize, SMEM_MMA);

    k_prep<<<NQT + DD, RR>>>(wr, wrb, we);
    k_mma_table<<<dim3(NQT / QT, DD / DT), 256, SMEM_MMA>>>(web);
    k_scatter<<<B / ROWS_PER_BLK, 256>>>(t, (float4*)out);
}